// round 7
// baseline (speedup 1.0000x reference)
#include <cuda_runtime.h>
#include <cuda_fp16.h>

#define NMAX 50000
#define EMAX 800000
// D = 128, ED = 64, H = 4, U = 32, HU = 128

// ---- scratch (device globals) ----
__device__ float  g_q  [NMAX * 128];
__device__ __half g_kh [NMAX * 128];
__device__ __half g_vh [NMAX * 128];
__device__ __half g_mkh[NMAX * 256];     // Mk[n][h*64 + c], fp16
__device__ float  g_kb [NMAX * 4];       // kb[n][h]
__device__ int    g_rowptr[NMAX + 1];
__device__ float  g_scores[EMAX * 4];    // scores[e][h]

// ============================================================================
// K1: q,k,v = X @ W{q,k,v} + b — [N,128]@[128,128], blockIdx.y selects matrix.
//     Scalar fp32 FFMA register tile. q written fp32; k,v fp16.
// ============================================================================
__global__ __launch_bounds__(256) void qkv_gemm_kernel(
    const float* __restrict__ X,
    const float* __restrict__ Wq, const float* __restrict__ bq,
    const float* __restrict__ Wk, const float* __restrict__ bk,
    const float* __restrict__ Wv, const float* __restrict__ bv,
    int N)
{
    __shared__ float As[32][129];   // [k][m], padded
    __shared__ float Bs[32][128];   // [k][n]

    const float* W; const float* bias;
    if (blockIdx.y == 0)      { W = Wq; bias = bq; }
    else if (blockIdx.y == 1) { W = Wk; bias = bk; }
    else                      { W = Wv; bias = bv; }
    const bool isQ = (blockIdx.y == 0);
    __half* OutH = (blockIdx.y == 1) ? g_kh : g_vh;

    const int row0 = blockIdx.x * 128;
    const int tid  = threadIdx.x;
    const int tx   = tid & 15;    // m-group
    const int ty   = tid >> 4;    // n-group

    float acc[8][8];
#pragma unroll
    for (int i = 0; i < 8; i++)
#pragma unroll
        for (int j = 0; j < 8; j++) acc[i][j] = 0.f;

    for (int kt = 0; kt < 128; kt += 32) {
#pragma unroll
        for (int i = 0; i < 4; i++) {
            int r = (tid >> 3) + i * 32;
            int c = (tid & 7) * 4;
            float4 a = make_float4(0.f, 0.f, 0.f, 0.f);
            if (row0 + r < N)
                a = *(const float4*)(X + (row0 + r) * 128 + kt + c);
            As[c + 0][r] = a.x;
            As[c + 1][r] = a.y;
            As[c + 2][r] = a.z;
            As[c + 3][r] = a.w;
        }
#pragma unroll
        for (int i = 0; i < 4; i++) {
            int kk = (tid >> 5) + i * 8;
            int nn = (tid & 31) * 4;
            *(float4*)&Bs[kk][nn] = *(const float4*)(W + (kt + kk) * 128 + nn);
        }
        __syncthreads();
#pragma unroll
        for (int k = 0; k < 32; k++) {
            float a[8], b[8];
#pragma unroll
            for (int i = 0; i < 8; i++) a[i] = As[k][tx * 8 + i];
            *(float4*)&b[0] = *(float4*)&Bs[k][ty * 8];
            *(float4*)&b[4] = *(float4*)&Bs[k][ty * 8 + 4];
#pragma unroll
            for (int i = 0; i < 8; i++)
#pragma unroll
                for (int j = 0; j < 8; j++)
                    acc[i][j] = fmaf(a[i], b[j], acc[i][j]);
        }
        __syncthreads();
    }

#pragma unroll
    for (int i = 0; i < 8; i++) {
        int r = row0 + tx * 8 + i;
        if (r < N) {
            float o[8];
#pragma unroll
            for (int j = 0; j < 8; j++) o[j] = acc[i][j] + bias[ty * 8 + j];
            if (isQ) {
                *(float4*)(g_q + r * 128 + ty * 8)     = make_float4(o[0], o[1], o[2], o[3]);
                *(float4*)(g_q + r * 128 + ty * 8 + 4) = make_float4(o[4], o[5], o[6], o[7]);
            } else {
                __half2 h[4];
                h[0] = __float22half2_rn(make_float2(o[0], o[1]));
                h[1] = __float22half2_rn(make_float2(o[2], o[3]));
                h[2] = __float22half2_rn(make_float2(o[4], o[5]));
                h[3] = __float22half2_rn(make_float2(o[6], o[7]));
                *(uint4*)(OutH + r * 128 + ty * 8) = *(uint4*)h;
            }
        }
    }
}

// ============================================================================
// K2: Mk[n,h,c] = sum_u We[c, h*32+u] * k[n,h,u] (fp16 out);
//     kb[n,h] = sum_u be[hu]*k[n,h,u]
// ============================================================================
__global__ __launch_bounds__(256) void mk_kernel(
    const float* __restrict__ We, const float* __restrict__ be, int N)
{
    __shared__ float WeT[128][65];   // [hu][c], padded
    __shared__ float ks[16][128];

    const int tid = threadIdx.x;
    const int n0  = blockIdx.x * 16;

    for (int i = tid; i < 64 * 128; i += 256) {
        int c  = i >> 7;
        int hu = i & 127;
        WeT[hu][c] = We[i];
    }
    for (int i = tid; i < 16 * 64; i += 256) {   // half2 granules
        int nl  = i >> 6;
        int off = (i & 63) * 2;
        __half2 hv = __half2half2(__float2half(0.f));
        if (n0 + nl < N) hv = *(const __half2*)(g_kh + (n0 + nl) * 128 + off);
        float2 f = __half22float2(hv);
        ks[nl][off]     = f.x;
        ks[nl][off + 1] = f.y;
    }
    __syncthreads();

    const int h = tid >> 6, c = tid & 63;
#pragma unroll 1
    for (int nl = 0; nl < 16; nl++) {
        if (n0 + nl >= N) break;
        float s = 0.f;
#pragma unroll
        for (int u = 0; u < 32; u++)
            s = fmaf(ks[nl][h * 32 + u], WeT[h * 32 + u][c], s);
        g_mkh[(n0 + nl) * 256 + h * 64 + c] = __float2half_rn(s);
    }
    if (tid < 64) {
        int nl = tid >> 2, h2 = tid & 3;
        if (n0 + nl < N) {
            float s = 0.f;
#pragma unroll
            for (int u = 0; u < 32; u++)
                s = fmaf(be[h2 * 32 + u], ks[nl][h2 * 32 + u], s);
            g_kb[(n0 + nl) * 4 + h2] = s;
        }
    }
}

// ============================================================================
// K3: rowptr[n] = lower_bound(src, n)  (src sorted)
// ============================================================================
__global__ void rowptr_kernel(const int* __restrict__ src, int E, int N)
{
    int n = blockIdx.x * blockDim.x + threadIdx.x;
    if (n > N) return;
    int lo = 0, hi = E;
    while (lo < hi) {
        int mid = (lo + hi) >> 1;
        if (src[mid] < n) lo = mid + 1; else hi = mid;
    }
    g_rowptr[n] = lo;
}

// ============================================================================
// K4a: score kernel — 8 lanes per edge, 4 edges per warp, fully parallel.
//   lane sl (0..7): owns hu = 16sl..16sl+15 (q·k half of head sl>>1)
//                   and c = (sl&1)*32..+31 of head sl>>1 (ef·Mk half).
//   One shfl_xor(1) completes score[e][sl>>1].
// ============================================================================
__global__ __launch_bounds__(256) void score_kernel(
    const float* __restrict__ EF,
    const int* __restrict__ src, const int* __restrict__ dst, int E)
{
    const int tid  = threadIdx.x;
    const int lane = tid & 31;
    const int wglob = blockIdx.x * 8 + (tid >> 5);
    const int g  = lane >> 3;      // edge slot 0..3
    const int sl = lane & 7;
    const int e  = wglob * 4 + g;
    if (e >= E) return;

    const int n  = src[e];
    const int d  = dst[e];
    const int hm = sl >> 1;          // head for this lane
    const int ch = (sl & 1) * 32;    // c half

    // ---- q·k over hu = 16sl..16sl+15 ----
    const float4* qp = (const float4*)(g_q + (size_t)n * 128 + sl * 16);
    const uint4*  kp = (const uint4*)(g_kh + (size_t)d * 128 + sl * 16);
    const float4 q0 = qp[0], q1 = qp[1], q2 = qp[2], q3 = qp[3];
    const uint4  k0 = kp[0], k1 = kp[1];

    float t = 0.f;
    float2 a;
    a = __half22float2(*(const __half2*)&k0.x); t = fmaf(q0.x, a.x, t); t = fmaf(q0.y, a.y, t);
    a = __half22float2(*(const __half2*)&k0.y); t = fmaf(q0.z, a.x, t); t = fmaf(q0.w, a.y, t);
    a = __half22float2(*(const __half2*)&k0.z); t = fmaf(q1.x, a.x, t); t = fmaf(q1.y, a.y, t);
    a = __half22float2(*(const __half2*)&k0.w); t = fmaf(q1.z, a.x, t); t = fmaf(q1.w, a.y, t);
    a = __half22float2(*(const __half2*)&k1.x); t = fmaf(q2.x, a.x, t); t = fmaf(q2.y, a.y, t);
    a = __half22float2(*(const __half2*)&k1.y); t = fmaf(q2.z, a.x, t); t = fmaf(q2.w, a.y, t);
    a = __half22float2(*(const __half2*)&k1.z); t = fmaf(q3.x, a.x, t); t = fmaf(q3.y, a.y, t);
    a = __half22float2(*(const __half2*)&k1.w); t = fmaf(q3.z, a.x, t); t = fmaf(q3.w, a.y, t);

    // ---- ef·Mk over c = ch..ch+31 of head hm ----
    const uint4*  mkp = (const uint4*) (g_mkh + (size_t)d * 256 + hm * 64 + ch);
    const float4* efp = (const float4*)(EF + (size_t)e * 64 + ch);
#pragma unroll
    for (int i = 0; i < 4; i++) {
        const uint4  mk = mkp[i];
        const float4 f0 = __ldcs(efp + 2 * i);
        const float4 f1 = __ldcs(efp + 2 * i + 1);
        a = __half22float2(*(const __half2*)&mk.x); t = fmaf(f0.x, a.x, t); t = fmaf(f0.y, a.y, t);
        a = __half22float2(*(const __half2*)&mk.y); t = fmaf(f0.z, a.x, t); t = fmaf(f0.w, a.y, t);
        a = __half22float2(*(const __half2*)&mk.z); t = fmaf(f1.x, a.x, t); t = fmaf(f1.y, a.y, t);
        a = __half22float2(*(const __half2*)&mk.w); t = fmaf(f1.z, a.x, t); t = fmaf(f1.w, a.y, t);
    }

    // pairwise reduce → full head score
    t += __shfl_xor_sync(0xffffffffu, t, 1);
    if ((sl & 1) == 0)
        g_scores[(size_t)e * 4 + hm] = t + g_kb[(size_t)d * 4 + hm];
}

// ============================================================================
// K4b: aggregate kernel — one warp per node; loop is only
//      {score load, v gather, exp, fma} — no shuffles. Unroll-4.
// ============================================================================
__global__ __launch_bounds__(256) void aggregate_kernel(
    const int* __restrict__ dst,
    const float* __restrict__ Wo, const float* __restrict__ bo,
    float* __restrict__ out, int N)
{
    __shared__ float sWo[128 * 32];
    __shared__ float sbo[32];
    const int tid = threadIdx.x;
    for (int i = tid; i < 1024; i += 256)
        ((float4*)sWo)[i] = ((const float4*)Wo)[i];
    if (tid < 32) sbo[tid] = bo[tid];
    __syncthreads();

    const int lane = tid & 31, warp = tid >> 5;
    const int n = blockIdx.x * 8 + warp;
    if (n >= N) return;

    const int hl = lane >> 3;
    const int e0 = g_rowptr[n], e1 = g_rowptr[n + 1];

    float  m    = -1e30f;
    float  sexp = 0.f;
    float4 acc  = make_float4(0.f, 0.f, 0.f, 0.f);

    int e = e0;
#pragma unroll 1
    for (; e + 4 <= e1; e += 4) {
        const int d0 = dst[e],     d1 = dst[e + 1];
        const int d2 = dst[e + 2], d3 = dst[e + 3];
        const float s0 = g_scores[(size_t)(e    ) * 4 + hl];
        const float s1 = g_scores[(size_t)(e + 1) * 4 + hl];
        const float s2 = g_scores[(size_t)(e + 2) * 4 + hl];
        const float s3 = g_scores[(size_t)(e + 3) * 4 + hl];
        const uint2 r0 = *(const uint2*)(g_vh + (size_t)d0 * 128 + lane * 4);
        const uint2 r1 = *(const uint2*)(g_vh + (size_t)d1 * 128 + lane * 4);
        const uint2 r2 = *(const uint2*)(g_vh + (size_t)d2 * 128 + lane * 4);
        const uint2 r3 = *(const uint2*)(g_vh + (size_t)d3 * 128 + lane * 4);

        const float mnew = fmaxf(fmaxf(m, fmaxf(s0, s1)), fmaxf(s2, s3));
        const float scale = __expf(m - mnew);
        const float w0 = __expf(s0 - mnew);
        const float w1 = __expf(s1 - mnew);
        const float w2 = __expf(s2 - mnew);
        const float w3 = __expf(s3 - mnew);
        sexp = fmaf(sexp, scale, (w0 + w1) + (w2 + w3));

        float2 p0 = __half22float2(*(const __half2*)&r0.x);
        float2 p1 = __half22float2(*(const __half2*)&r1.x);
        float2 p2 = __half22float2(*(const __half2*)&r2.x);
        float2 p3 = __half22float2(*(const __half2*)&r3.x);
        acc.x = fmaf(acc.x, scale, fmaf(w0, p0.x, w1 * p1.x) + fmaf(w2, p2.x, w3 * p3.x));
        acc.y = fmaf(acc.y, scale, fmaf(w0, p0.y, w1 * p1.y) + fmaf(w2, p2.y, w3 * p3.y));
        p0 = __half22float2(*(const __half2*)&r0.y);
        p1 = __half22float2(*(const __half2*)&r1.y);
        p2 = __half22float2(*(const __half2*)&r2.y);
        p3 = __half22float2(*(const __half2*)&r3.y);
        acc.z = fmaf(acc.z, scale, fmaf(w0, p0.x, w1 * p1.x) + fmaf(w2, p2.x, w3 * p3.x));
        acc.w = fmaf(acc.w, scale, fmaf(w0, p0.y, w1 * p1.y) + fmaf(w2, p2.y, w3 * p3.y));
        m = mnew;
    }
#pragma unroll 1
    for (; e < e1; e++) {
        const int d0 = dst[e];
        const float s0 = g_scores[(size_t)e * 4 + hl];
        const uint2 r0 = *(const uint2*)(g_vh + (size_t)d0 * 128 + lane * 4);
        const float mnew  = fmaxf(m, s0);
        const float scale = __expf(m - mnew);
        const float w0    = __expf(s0 - mnew);
        sexp = fmaf(sexp, scale, w0);
        const float2 p0 = __half22float2(*(const __half2*)&r0.x);
        const float2 p1 = __half22float2(*(const __half2*)&r0.y);
        acc.x = fmaf(acc.x, scale, w0 * p0.x);
        acc.y = fmaf(acc.y, scale, w0 * p0.y);
        acc.z = fmaf(acc.z, scale, w0 * p1.x);
        acc.w = fmaf(acc.w, scale, w0 * p1.y);
        m = mnew;
    }

    const float inv = (sexp > 0.f) ? (1.0f / sexp) : 0.f;
    acc.x *= inv; acc.y *= inv; acc.z *= inv; acc.w *= inv;

    // output epilogue: out[n, j=lane] = relu(sum_hu attended[hu]*Wo[hu,j] + bo[j])
    float o = sbo[lane];
#pragma unroll
    for (int p = 0; p < 32; p++) {
        const float ax = __shfl_sync(0xffffffffu, acc.x, p);
        const float ay = __shfl_sync(0xffffffffu, acc.y, p);
        const float az = __shfl_sync(0xffffffffu, acc.z, p);
        const float aw = __shfl_sync(0xffffffffu, acc.w, p);
        o = fmaf(ax, sWo[(4 * p + 0) * 32 + lane], o);
        o = fmaf(ay, sWo[(4 * p + 1) * 32 + lane], o);
        o = fmaf(az, sWo[(4 * p + 2) * 32 + lane], o);
        o = fmaf(aw, sWo[(4 * p + 3) * 32 + lane], o);
    }
    out[n * 32 + lane] = fmaxf(o, 0.f);
}

// ============================================================================
// launch
// ============================================================================
extern "C" void kernel_launch(void* const* d_in, const int* in_sizes, int n_in,
                              void* d_out, int out_size)
{
    const float* X  = (const float*)d_in[0];
    const int*   EI = (const int*)  d_in[1];   // [2,E]: src then dst
    const float* EF = (const float*)d_in[2];
    const float* Wq = (const float*)d_in[3];
    const float* bq = (const float*)d_in[4];
    const float* Wk = (const float*)d_in[5];
    const float* bk = (const float*)d_in[6];
    const float* Wv = (const float*)d_in[7];
    const float* bv = (const float*)d_in[8];
    const float* We = (const float*)d_in[9];
    const float* be = (const float*)d_in[10];
    const float* Wo = (const float*)d_in[11];
    const float* bo = (const float*)d_in[12];

    const int N = in_sizes[0] / 128;
    const int E = in_sizes[1] / 2;

    dim3 g1((N + 127) / 128, 3);
    qkv_gemm_kernel<<<g1, 256>>>(X, Wq, bq, Wk, bk, Wv, bv, N);
    mk_kernel<<<(N + 15) / 16, 256>>>(We, be, N);
    rowptr_kernel<<<(N + 1 + 255) / 256, 256>>>(EI, E, N);
    score_kernel<<<(E + 31) / 32, 256>>>(EF, EI, EI + E, E);
    aggregate_kernel<<<(N + 7) / 8, 256>>>(EI + E, Wo, bo, (float*)d_out, N);
}

// round 8
// speedup vs baseline: 1.0743x; 1.0743x over previous
#include <cuda_runtime.h>
#include <cuda_fp16.h>

#define NMAX 50000
#define EMAX 800000
// D = 128, ED = 64, H = 4, U = 32, HU = 128

// ---- scratch (device globals) ----
__device__ float  g_q  [NMAX * 128];
__device__ __half g_kh [NMAX * 128];
__device__ __half g_vh [NMAX * 128];
__device__ __half g_mkh[NMAX * 256];     // Mk[n][h*64 + c], fp16
__device__ float  g_kb [NMAX * 4];       // kb[n][h]
__device__ int    g_rowptr[NMAX + 1];
__device__ float  g_scores[EMAX * 4];    // scores[e][h]

// ============================================================================
// K1: q,k,v = X @ W{q,k,v} + b — [N,128]@[128,128], blockIdx.y selects matrix.
// ============================================================================
__global__ __launch_bounds__(256) void qkv_gemm_kernel(
    const float* __restrict__ X,
    const float* __restrict__ Wq, const float* __restrict__ bq,
    const float* __restrict__ Wk, const float* __restrict__ bk,
    const float* __restrict__ Wv, const float* __restrict__ bv,
    int N)
{
    __shared__ float As[32][129];
    __shared__ float Bs[32][128];

    const float* W; const float* bias;
    if (blockIdx.y == 0)      { W = Wq; bias = bq; }
    else if (blockIdx.y == 1) { W = Wk; bias = bk; }
    else                      { W = Wv; bias = bv; }
    const bool isQ = (blockIdx.y == 0);
    __half* OutH = (blockIdx.y == 1) ? g_kh : g_vh;

    const int row0 = blockIdx.x * 128;
    const int tid  = threadIdx.x;
    const int tx   = tid & 15;
    const int ty   = tid >> 4;

    float acc[8][8];
#pragma unroll
    for (int i = 0; i < 8; i++)
#pragma unroll
        for (int j = 0; j < 8; j++) acc[i][j] = 0.f;

    for (int kt = 0; kt < 128; kt += 32) {
#pragma unroll
        for (int i = 0; i < 4; i++) {
            int r = (tid >> 3) + i * 32;
            int c = (tid & 7) * 4;
            float4 a = make_float4(0.f, 0.f, 0.f, 0.f);
            if (row0 + r < N)
                a = *(const float4*)(X + (row0 + r) * 128 + kt + c);
            As[c + 0][r] = a.x;
            As[c + 1][r] = a.y;
            As[c + 2][r] = a.z;
            As[c + 3][r] = a.w;
        }
#pragma unroll
        for (int i = 0; i < 4; i++) {
            int kk = (tid >> 5) + i * 8;
            int nn = (tid & 31) * 4;
            *(float4*)&Bs[kk][nn] = *(const float4*)(W + (kt + kk) * 128 + nn);
        }
        __syncthreads();
#pragma unroll
        for (int k = 0; k < 32; k++) {
            float a[8], b[8];
#pragma unroll
            for (int i = 0; i < 8; i++) a[i] = As[k][tx * 8 + i];
            *(float4*)&b[0] = *(float4*)&Bs[k][ty * 8];
            *(float4*)&b[4] = *(float4*)&Bs[k][ty * 8 + 4];
#pragma unroll
            for (int i = 0; i < 8; i++)
#pragma unroll
                for (int j = 0; j < 8; j++)
                    acc[i][j] = fmaf(a[i], b[j], acc[i][j]);
        }
        __syncthreads();
    }

#pragma unroll
    for (int i = 0; i < 8; i++) {
        int r = row0 + tx * 8 + i;
        if (r < N) {
            float o[8];
#pragma unroll
            for (int j = 0; j < 8; j++) o[j] = acc[i][j] + bias[ty * 8 + j];
            if (isQ) {
                *(float4*)(g_q + r * 128 + ty * 8)     = make_float4(o[0], o[1], o[2], o[3]);
                *(float4*)(g_q + r * 128 + ty * 8 + 4) = make_float4(o[4], o[5], o[6], o[7]);
            } else {
                __half2 h[4];
                h[0] = __float22half2_rn(make_float2(o[0], o[1]));
                h[1] = __float22half2_rn(make_float2(o[2], o[3]));
                h[2] = __float22half2_rn(make_float2(o[4], o[5]));
                h[3] = __float22half2_rn(make_float2(o[6], o[7]));
                *(uint4*)(OutH + r * 128 + ty * 8) = *(uint4*)h;
            }
        }
    }
}

// ============================================================================
// K2: Mk[n,h,c] = sum_u We[c, h*32+u] * k[n,h,u] (fp16 out);
//     kb[n,h] = sum_u be[hu]*k[n,h,u]
// ============================================================================
__global__ __launch_bounds__(256) void mk_kernel(
    const float* __restrict__ We, const float* __restrict__ be, int N)
{
    __shared__ float WeT[128][65];
    __shared__ float ks[16][128];

    const int tid = threadIdx.x;
    const int n0  = blockIdx.x * 16;

    for (int i = tid; i < 64 * 128; i += 256) {
        int c  = i >> 7;
        int hu = i & 127;
        WeT[hu][c] = We[i];
    }
    for (int i = tid; i < 16 * 64; i += 256) {
        int nl  = i >> 6;
        int off = (i & 63) * 2;
        __half2 hv = __half2half2(__float2half(0.f));
        if (n0 + nl < N) hv = *(const __half2*)(g_kh + (n0 + nl) * 128 + off);
        float2 f = __half22float2(hv);
        ks[nl][off]     = f.x;
        ks[nl][off + 1] = f.y;
    }
    __syncthreads();

    const int h = tid >> 6, c = tid & 63;
#pragma unroll 1
    for (int nl = 0; nl < 16; nl++) {
        if (n0 + nl >= N) break;
        float s = 0.f;
#pragma unroll
        for (int u = 0; u < 32; u++)
            s = fmaf(ks[nl][h * 32 + u], WeT[h * 32 + u][c], s);
        g_mkh[(n0 + nl) * 256 + h * 64 + c] = __float2half_rn(s);
    }
    if (tid < 64) {
        int nl = tid >> 2, h2 = tid & 3;
        if (n0 + nl < N) {
            float s = 0.f;
#pragma unroll
            for (int u = 0; u < 32; u++)
                s = fmaf(be[h2 * 32 + u], ks[nl][h2 * 32 + u], s);
            g_kb[(n0 + nl) * 4 + h2] = s;
        }
    }
}

// ============================================================================
// K3: rowptr[n] = lower_bound(src, n)  (src sorted)
// ============================================================================
__global__ void rowptr_kernel(const int* __restrict__ src, int E, int N)
{
    int n = blockIdx.x * blockDim.x + threadIdx.x;
    if (n > N) return;
    int lo = 0, hi = E;
    while (lo < hi) {
        int mid = (lo + hi) >> 1;
        if (src[mid] < n) lo = mid + 1; else hi = mid;
    }
    g_rowptr[n] = lo;
}

// ============================================================================
// K4a: score kernel v2 — line-coherent gathers.
//   Warp = 4 edges. EF staged via smem (coalesced). 8 lanes per edge:
//   lane sl owns c = 8sl..8sl+7 (all heads, mk 1 line/instr) and
//   hu = 16sl..16sl+15 (q·k, folds into head sl>>1). 4-head butterfly reduce.
// ============================================================================
__global__ __launch_bounds__(256) void score_kernel(
    const float* __restrict__ EF,
    const int* __restrict__ src, const int* __restrict__ dst, int E)
{
    __shared__ float sEF[8][256];   // 8 warps x (4 edges x 64 floats)

    const int tid  = threadIdx.x;
    const int lane = tid & 31;
    const int warp = tid >> 5;
    const int ebase = (blockIdx.x * 8 + warp) * 4;

    // cooperative EF stage: 64 float4 per warp, fully coalesced
#pragma unroll
    for (int j = 0; j < 2; j++) {
        const int f = j * 32 + lane;            // float4 index 0..63
        const int ee = ebase + (f >> 4);
        if (ee < E) {
            const float4 v = __ldcs((const float4*)(EF + (size_t)ee * 64) + (f & 15));
            *(float4*)&sEF[warp][f * 4] = v;
        }
    }
    __syncwarp();

    const int g  = lane >> 3;
    const int sl = lane & 7;
    int e = ebase + g;
    const bool valid = (e < E);
    if (!valid) e = E - 1;                       // clamp: lanes stay active for shfl

    const int n = src[e];
    const int d = dst[e];

    // lane's ef chunk: 8 floats (read once, reused for all 4 heads)
    float ef0x, ef0y, ef0z, ef0w, ef1x, ef1y, ef1z, ef1w;
    {
        const float4 a = *(const float4*)&sEF[warp][g * 64 + sl * 8];
        const float4 b = *(const float4*)&sEF[warp][g * 64 + sl * 8 + 4];
        ef0x = a.x; ef0y = a.y; ef0z = a.z; ef0w = a.w;
        ef1x = b.x; ef1y = b.y; ef1z = b.z; ef1w = b.w;
    }

    float t0 = 0.f, t1 = 0.f, t2 = 0.f, t3 = 0.f;

    // mk term: head i at uint4 index i*8 + sl → 8 contiguous uint4 per instr per edge
    {
        const uint4* mkp = (const uint4*)(g_mkh + (size_t)d * 256);
        const uint4 m0 = mkp[0 * 8 + sl];
        const uint4 m1 = mkp[1 * 8 + sl];
        const uint4 m2 = mkp[2 * 8 + sl];
        const uint4 m3 = mkp[3 * 8 + sl];
        float2 a;
#define DOT8(T, M)                                                              \
        a = __half22float2(*(const __half2*)&(M).x); T = fmaf(ef0x, a.x, T); T = fmaf(ef0y, a.y, T); \
        a = __half22float2(*(const __half2*)&(M).y); T = fmaf(ef0z, a.x, T); T = fmaf(ef0w, a.y, T); \
        a = __half22float2(*(const __half2*)&(M).z); T = fmaf(ef1x, a.x, T); T = fmaf(ef1y, a.y, T); \
        a = __half22float2(*(const __half2*)&(M).w); T = fmaf(ef1z, a.x, T); T = fmaf(ef1w, a.y, T);
        DOT8(t0, m0)
        DOT8(t1, m1)
        DOT8(t2, m2)
        DOT8(t3, m3)
#undef DOT8
    }

    // q·k term over hu = 16sl..16sl+15 (head sl>>1), line-coherent per instr
    {
        const float4* qp = (const float4*)(g_q  + (size_t)n * 128 + sl * 16);
        const uint4*  kp = (const uint4*) (g_kh + (size_t)d * 128 + sl * 16);
        const float4 q0 = qp[0], q1 = qp[1], q2 = qp[2], q3 = qp[3];
        const uint4  k0 = kp[0], k1 = kp[1];
        float qk = 0.f;
        float2 a;
        a = __half22float2(*(const __half2*)&k0.x); qk = fmaf(q0.x, a.x, qk); qk = fmaf(q0.y, a.y, qk);
        a = __half22float2(*(const __half2*)&k0.y); qk = fmaf(q0.z, a.x, qk); qk = fmaf(q0.w, a.y, qk);
        a = __half22float2(*(const __half2*)&k0.z); qk = fmaf(q1.x, a.x, qk); qk = fmaf(q1.y, a.y, qk);
        a = __half22float2(*(const __half2*)&k0.w); qk = fmaf(q1.z, a.x, qk); qk = fmaf(q1.w, a.y, qk);
        a = __half22float2(*(const __half2*)&k1.x); qk = fmaf(q2.x, a.x, qk); qk = fmaf(q2.y, a.y, qk);
        a = __half22float2(*(const __half2*)&k1.y); qk = fmaf(q2.z, a.x, qk); qk = fmaf(q2.w, a.y, qk);
        a = __half22float2(*(const __half2*)&k1.z); qk = fmaf(q3.x, a.x, qk); qk = fmaf(q3.y, a.y, qk);
        a = __half22float2(*(const __half2*)&k1.w); qk = fmaf(q3.z, a.x, qk); qk = fmaf(q3.w, a.y, qk);

        const int hq = sl >> 1;
        t0 += (hq == 0) ? qk : 0.f;
        t1 += (hq == 1) ? qk : 0.f;
        t2 += (hq == 2) ? qk : 0.f;
        t3 += (hq == 3) ? qk : 0.f;
    }

    // butterfly reduce over the 8-lane edge group
#pragma unroll
    for (int o = 1; o <= 4; o <<= 1) {
        t0 += __shfl_xor_sync(0xffffffffu, t0, o);
        t1 += __shfl_xor_sync(0xffffffffu, t1, o);
        t2 += __shfl_xor_sync(0xffffffffu, t2, o);
        t3 += __shfl_xor_sync(0xffffffffu, t3, o);
    }

    if (valid && sl < 4) {
        const float th = (sl == 0) ? t0 : (sl == 1) ? t1 : (sl == 2) ? t2 : t3;
        g_scores[(size_t)e * 4 + sl] = th + g_kb[(size_t)d * 4 + sl];
    }
}

// ============================================================================
// K4b: aggregate kernel — one warp per node; {score load, v gather, exp, fma}.
// ============================================================================
__global__ __launch_bounds__(256) void aggregate_kernel(
    const int* __restrict__ dst,
    const float* __restrict__ Wo, const float* __restrict__ bo,
    float* __restrict__ out, int N)
{
    __shared__ float sWo[128 * 32];
    __shared__ float sbo[32];
    const int tid = threadIdx.x;
    for (int i = tid; i < 1024; i += 256)
        ((float4*)sWo)[i] = ((const float4*)Wo)[i];
    if (tid < 32) sbo[tid] = bo[tid];
    __syncthreads();

    const int lane = tid & 31, warp = tid >> 5;
    const int n = blockIdx.x * 8 + warp;
    if (n >= N) return;

    const int hl = lane >> 3;
    const int e0 = g_rowptr[n], e1 = g_rowptr[n + 1];

    float  m    = -1e30f;
    float  sexp = 0.f;
    float4 acc  = make_float4(0.f, 0.f, 0.f, 0.f);

    int e = e0;
#pragma unroll 1
    for (; e + 4 <= e1; e += 4) {
        const int d0 = dst[e],     d1 = dst[e + 1];
        const int d2 = dst[e + 2], d3 = dst[e + 3];
        const float s0 = g_scores[(size_t)(e    ) * 4 + hl];
        const float s1 = g_scores[(size_t)(e + 1) * 4 + hl];
        const float s2 = g_scores[(size_t)(e + 2) * 4 + hl];
        const float s3 = g_scores[(size_t)(e + 3) * 4 + hl];
        const uint2 r0 = *(const uint2*)(g_vh + (size_t)d0 * 128 + lane * 4);
        const uint2 r1 = *(const uint2*)(g_vh + (size_t)d1 * 128 + lane * 4);
        const uint2 r2 = *(const uint2*)(g_vh + (size_t)d2 * 128 + lane * 4);
        const uint2 r3 = *(const uint2*)(g_vh + (size_t)d3 * 128 + lane * 4);

        const float mnew = fmaxf(fmaxf(m, fmaxf(s0, s1)), fmaxf(s2, s3));
        const float scale = __expf(m - mnew);
        const float w0 = __expf(s0 - mnew);
        const float w1 = __expf(s1 - mnew);
        const float w2 = __expf(s2 - mnew);
        const float w3 = __expf(s3 - mnew);
        sexp = fmaf(sexp, scale, (w0 + w1) + (w2 + w3));

        float2 p0 = __half22float2(*(const __half2*)&r0.x);
        float2 p1 = __half22float2(*(const __half2*)&r1.x);
        float2 p2 = __half22float2(*(const __half2*)&r2.x);
        float2 p3 = __half22float2(*(const __half2*)&r3.x);
        acc.x = fmaf(acc.x, scale, fmaf(w0, p0.x, w1 * p1.x) + fmaf(w2, p2.x, w3 * p3.x));
        acc.y = fmaf(acc.y, scale, fmaf(w0, p0.y, w1 * p1.y) + fmaf(w2, p2.y, w3 * p3.y));
        p0 = __half22float2(*(const __half2*)&r0.y);
        p1 = __half22float2(*(const __half2*)&r1.y);
        p2 = __half22float2(*(const __half2*)&r2.y);
        p3 = __half22float2(*(const __half2*)&r3.y);
        acc.z = fmaf(acc.z, scale, fmaf(w0, p0.x, w1 * p1.x) + fmaf(w2, p2.x, w3 * p3.x));
        acc.w = fmaf(acc.w, scale, fmaf(w0, p0.y, w1 * p1.y) + fmaf(w2, p2.y, w3 * p3.y));
        m = mnew;
    }
#pragma unroll 1
    for (; e < e1; e++) {
        const int d0 = dst[e];
        const float s0 = g_scores[(size_t)e * 4 + hl];
        const uint2 r0 = *(const uint2*)(g_vh + (size_t)d0 * 128 + lane * 4);
        const float mnew  = fmaxf(m, s0);
        const float scale = __expf(m - mnew);
        const float w0    = __expf(s0 - mnew);
        sexp = fmaf(sexp, scale, w0);
        const float2 p0 = __half22float2(*(const __half2*)&r0.x);
        const float2 p1 = __half22float2(*(const __half2*)&r0.y);
        acc.x = fmaf(acc.x, scale, w0 * p0.x);
        acc.y = fmaf(acc.y, scale, w0 * p0.y);
        acc.z = fmaf(acc.z, scale, w0 * p1.x);
        acc.w = fmaf(acc.w, scale, w0 * p1.y);
        m = mnew;
    }

    const float inv = (sexp > 0.f) ? (1.0f / sexp) : 0.f;
    acc.x *= inv; acc.y *= inv; acc.z *= inv; acc.w *= inv;

    float o = sbo[lane];
#pragma unroll
    for (int p = 0; p < 32; p++) {
        const float ax = __shfl_sync(0xffffffffu, acc.x, p);
        const float ay = __shfl_sync(0xffffffffu, acc.y, p);
        const float az = __shfl_sync(0xffffffffu, acc.z, p);
        const float aw = __shfl_sync(0xffffffffu, acc.w, p);
        o = fmaf(ax, sWo[(4 * p + 0) * 32 + lane], o);
        o = fmaf(ay, sWo[(4 * p + 1) * 32 + lane], o);
        o = fmaf(az, sWo[(4 * p + 2) * 32 + lane], o);
        o = fmaf(aw, sWo[(4 * p + 3) * 32 + lane], o);
    }
    out[n * 32 + lane] = fmaxf(o, 0.f);
}

// ============================================================================
// launch
// ============================================================================
extern "C" void kernel_launch(void* const* d_in, const int* in_sizes, int n_in,
                              void* d_out, int out_size)
{
    const float* X  = (const float*)d_in[0];
    const int*   EI = (const int*)  d_in[1];   // [2,E]: src then dst
    const float* EF = (const float*)d_in[2];
    const float* Wq = (const float*)d_in[3];
    const float* bq = (const float*)d_in[4];
    const float* Wk = (const float*)d_in[5];
    const float* bk = (const float*)d_in[6];
    const float* Wv = (const float*)d_in[7];
    const float* bv = (const float*)d_in[8];
    const float* We = (const float*)d_in[9];
    const float* be = (const float*)d_in[10];
    const float* Wo = (const float*)d_in[11];
    const float* bo = (const float*)d_in[12];

    const int N = in_sizes[0] / 128;
    const int E = in_sizes[1] / 2;

    dim3 g1((N + 127) / 128, 3);
    qkv_gemm_kernel<<<g1, 256>>>(X, Wq, bq, Wk, bk, Wv, bv, N);
    mk_kernel<<<(N + 15) / 16, 256>>>(We, be, N);
    rowptr_kernel<<<(N + 1 + 255) / 256, 256>>>(EI, E, N);
    score_kernel<<<(E + 31) / 32, 256>>>(EF, EI, EI + E, E);
    aggregate_kernel<<<(N + 7) / 8, 256>>>(EI + E, Wo, bo, (float*)d_out, N);
}

// round 12
// speedup vs baseline: 1.1800x; 1.0985x over previous
#include <cuda_runtime.h>
#include <cuda_fp16.h>

#define NMAX 50000
#define EMAX 800000
// D = 128, ED = 64, H = 4, U = 32, HU = 128

// ---- scratch (device globals) ----
__device__ float  g_q  [NMAX * 128];
__device__ __half g_kh [NMAX * 128];
__device__ __half g_vh [NMAX * 128];
__device__ __half g_mkh[NMAX * 256];     // Mk[n][h*64 + c], fp16
__device__ float  g_kb [NMAX * 4];       // kb[n][h]
__device__ int    g_rowptr[NMAX + 1];
__device__ float  g_scores[EMAX * 4];    // scores[e][h]

// ============================================================================
// K1: q,k,v = X @ W{q,k,v} + b — [N,128]@[128,128], blockIdx.y selects matrix.
// ============================================================================
__global__ __launch_bounds__(256) void qkv_gemm_kernel(
    const float* __restrict__ X,
    const float* __restrict__ Wq, const float* __restrict__ bq,
    const float* __restrict__ Wk, const float* __restrict__ bk,
    const float* __restrict__ Wv, const float* __restrict__ bv,
    int N)
{
    __shared__ float As[32][129];
    __shared__ float Bs[32][128];

    const float* W; const float* bias;
    if (blockIdx.y == 0)      { W = Wq; bias = bq; }
    else if (blockIdx.y == 1) { W = Wk; bias = bk; }
    else                      { W = Wv; bias = bv; }
    const bool isQ = (blockIdx.y == 0);
    __half* OutH = (blockIdx.y == 1) ? g_kh : g_vh;

    const int row0 = blockIdx.x * 128;
    const int tid  = threadIdx.x;
    const int tx   = tid & 15;
    const int ty   = tid >> 4;

    float acc[8][8];
#pragma unroll
    for (int i = 0; i < 8; i++)
#pragma unroll
        for (int j = 0; j < 8; j++) acc[i][j] = 0.f;

    for (int kt = 0; kt < 128; kt += 32) {
#pragma unroll
        for (int i = 0; i < 4; i++) {
            int r = (tid >> 3) + i * 32;
            int c = (tid & 7) * 4;
            float4 a = make_float4(0.f, 0.f, 0.f, 0.f);
            if (row0 + r < N)
                a = *(const float4*)(X + (row0 + r) * 128 + kt + c);
            As[c + 0][r] = a.x;
            As[c + 1][r] = a.y;
            As[c + 2][r] = a.z;
            As[c + 3][r] = a.w;
        }
#pragma unroll
        for (int i = 0; i < 4; i++) {
            int kk = (tid >> 5) + i * 8;
            int nn = (tid & 31) * 4;
            *(float4*)&Bs[kk][nn] = *(const float4*)(W + (kt + kk) * 128 + nn);
        }
        __syncthreads();
#pragma unroll
        for (int k = 0; k < 32; k++) {
            float a[8], b[8];
#pragma unroll
            for (int i = 0; i < 8; i++) a[i] = As[k][tx * 8 + i];
            *(float4*)&b[0] = *(float4*)&Bs[k][ty * 8];
            *(float4*)&b[4] = *(float4*)&Bs[k][ty * 8 + 4];
#pragma unroll
            for (int i = 0; i < 8; i++)
#pragma unroll
                for (int j = 0; j < 8; j++)
                    acc[i][j] = fmaf(a[i], b[j], acc[i][j]);
        }
        __syncthreads();
    }

#pragma unroll
    for (int i = 0; i < 8; i++) {
        int r = row0 + tx * 8 + i;
        if (r < N) {
            float o[8];
#pragma unroll
            for (int j = 0; j < 8; j++) o[j] = acc[i][j] + bias[ty * 8 + j];
            if (isQ) {
                *(float4*)(g_q + r * 128 + ty * 8)     = make_float4(o[0], o[1], o[2], o[3]);
                *(float4*)(g_q + r * 128 + ty * 8 + 4) = make_float4(o[4], o[5], o[6], o[7]);
            } else {
                __half2 h[4];
                h[0] = __float22half2_rn(make_float2(o[0], o[1]));
                h[1] = __float22half2_rn(make_float2(o[2], o[3]));
                h[2] = __float22half2_rn(make_float2(o[4], o[5]));
                h[3] = __float22half2_rn(make_float2(o[6], o[7]));
                *(uint4*)(OutH + r * 128 + ty * 8) = *(uint4*)h;
            }
        }
    }
}

// ============================================================================
// K2: Mk[n,h,c] = sum_u We[c, h*32+u] * k[n,h,u] (fp16 out);
//     kb[n,h] = sum_u be[hu]*k[n,h,u]
// ============================================================================
__global__ __launch_bounds__(256) void mk_kernel(
    const float* __restrict__ We, const float* __restrict__ be, int N)
{
    __shared__ float WeT[128][65];
    __shared__ float ks[16][128];

    const int tid = threadIdx.x;
    const int n0  = blockIdx.x * 16;

    for (int i = tid; i < 64 * 128; i += 256) {
        int c  = i >> 7;
        int hu = i & 127;
        WeT[hu][c] = We[i];
    }
    for (int i = tid; i < 16 * 64; i += 256) {
        int nl  = i >> 6;
        int off = (i & 63) * 2;
        __half2 hv = __half2half2(__float2half(0.f));
        if (n0 + nl < N) hv = *(const __half2*)(g_kh + (n0 + nl) * 128 + off);
        float2 f = __half22float2(hv);
        ks[nl][off]     = f.x;
        ks[nl][off + 1] = f.y;
    }
    __syncthreads();

    const int h = tid >> 6, c = tid & 63;
#pragma unroll 1
    for (int nl = 0; nl < 16; nl++) {
        if (n0 + nl >= N) break;
        float s = 0.f;
#pragma unroll
        for (int u = 0; u < 32; u++)
            s = fmaf(ks[nl][h * 32 + u], WeT[h * 32 + u][c], s);
        g_mkh[(n0 + nl) * 256 + h * 64 + c] = __float2half_rn(s);
    }
    if (tid < 64) {
        int nl = tid >> 2, h2 = tid & 3;
        if (n0 + nl < N) {
            float s = 0.f;
#pragma unroll
            for (int u = 0; u < 32; u++)
                s = fmaf(be[h2 * 32 + u], ks[nl][h2 * 32 + u], s);
            g_kb[(n0 + nl) * 4 + h2] = s;
        }
    }
}

// ============================================================================
// K3: rowptr[n] = lower_bound(src, n)  (src sorted)
// ============================================================================
__global__ void rowptr_kernel(const int* __restrict__ src, int E, int N)
{
    int n = blockIdx.x * blockDim.x + threadIdx.x;
    if (n > N) return;
    int lo = 0, hi = E;
    while (lo < hi) {
        int mid = (lo + hi) >> 1;
        if (src[mid] < n) lo = mid + 1; else hi = mid;
    }
    g_rowptr[n] = lo;
}

// ============================================================================
// K4a: score kernel v3 — ALL gathers line-coherent.
//   Warp = 4 edges, 8 lanes/edge. EF staged via smem.
//   mk:  head i at uint4 idx i*8+sl         → 1 line/instr  (4 wf/edge)
//   q:   head i: float4 at byte i*128+sl*16 → 1 line/instr  (4 wf/edge)
//   k:   head i: uint2  at byte i*64 +sl*8  → 64B/instr     (4 wf/edge)
//   Every lane contributes q·k AND ef·Mk partials to ALL 4 head
//   accumulators t0..t3; one 3-level butterfly finishes all heads.
// ============================================================================
__global__ __launch_bounds__(256) void score_kernel(
    const float* __restrict__ EF,
    const int* __restrict__ src, const int* __restrict__ dst, int E)
{
    __shared__ float sEF[8][256];   // 8 warps x (4 edges x 64 floats)

    const int tid  = threadIdx.x;
    const int lane = tid & 31;
    const int warp = tid >> 5;
    const int ebase = (blockIdx.x * 8 + warp) * 4;

    // cooperative EF stage: 64 float4 per warp, fully coalesced
#pragma unroll
    for (int j = 0; j < 2; j++) {
        const int f = j * 32 + lane;            // float4 index 0..63
        const int ee = ebase + (f >> 4);
        if (ee < E) {
            const float4 v = __ldcs((const float4*)(EF + (size_t)ee * 64) + (f & 15));
            *(float4*)&sEF[warp][f * 4] = v;
        }
    }
    __syncwarp();

    const int g  = lane >> 3;
    const int sl = lane & 7;
    int e = ebase + g;
    const bool valid = (e < E);
    if (!valid) e = E - 1;                       // clamp: lanes stay active for shfl

    const int n = src[e];
    const int d = dst[e];

    // lane's ef chunk: 8 floats (c = 8sl..8sl+7), reused for all 4 heads
    float ef0x, ef0y, ef0z, ef0w, ef1x, ef1y, ef1z, ef1w;
    {
        const float4 a = *(const float4*)&sEF[warp][g * 64 + sl * 8];
        const float4 b = *(const float4*)&sEF[warp][g * 64 + sl * 8 + 4];
        ef0x = a.x; ef0y = a.y; ef0z = a.z; ef0w = a.w;
        ef1x = b.x; ef1y = b.y; ef1z = b.z; ef1w = b.w;
    }

    float t0 = 0.f, t1 = 0.f, t2 = 0.f, t3 = 0.f;

    // ---- mk term: head i at uint4 index i*8 + sl (1 line/instr/edge) ----
    {
        const uint4* mkp = (const uint4*)(g_mkh + (size_t)d * 256);
        const uint4 m0 = mkp[0 * 8 + sl];
        const uint4 m1 = mkp[1 * 8 + sl];
        const uint4 m2 = mkp[2 * 8 + sl];
        const uint4 m3 = mkp[3 * 8 + sl];
        float2 a;
#define DOT8(T, M)                                                              \
        a = __half22float2(*(const __half2*)&(M).x); T = fmaf(ef0x, a.x, T); T = fmaf(ef0y, a.y, T); \
        a = __half22float2(*(const __half2*)&(M).y); T = fmaf(ef0z, a.x, T); T = fmaf(ef0w, a.y, T); \
        a = __half22float2(*(const __half2*)&(M).z); T = fmaf(ef1x, a.x, T); T = fmaf(ef1y, a.y, T); \
        a = __half22float2(*(const __half2*)&(M).w); T = fmaf(ef1z, a.x, T); T = fmaf(ef1w, a.y, T);
        DOT8(t0, m0)
        DOT8(t1, m1)
        DOT8(t2, m2)
        DOT8(t3, m3)
#undef DOT8
    }

    // ---- q·k term: head i, lane owns u = sl*4..sl*4+3 (line-coherent) ----
    {
        const float* qrow = g_q  + (size_t)n * 128;
        const __half* krow = g_kh + (size_t)d * 128;
        float2 a;
#define QK4(T, I)                                                               \
        {                                                                       \
            const float4 qq = *(const float4*)(qrow + (I) * 32 + sl * 4);       \
            const uint2  kk = *(const uint2*) (krow + (I) * 32 + sl * 4);       \
            a = __half22float2(*(const __half2*)&kk.x);                         \
            T = fmaf(qq.x, a.x, T); T = fmaf(qq.y, a.y, T);                     \
            a = __half22float2(*(const __half2*)&kk.y);                         \
            T = fmaf(qq.z, a.x, T); T = fmaf(qq.w, a.y, T);                     \
        }
        QK4(t0, 0)
        QK4(t1, 1)
        QK4(t2, 2)
        QK4(t3, 3)
#undef QK4
    }

    // butterfly reduce over the 8-lane edge group (all 4 heads at once)
#pragma unroll
    for (int o = 1; o <= 4; o <<= 1) {
        t0 += __shfl_xor_sync(0xffffffffu, t0, o);
        t1 += __shfl_xor_sync(0xffffffffu, t1, o);
        t2 += __shfl_xor_sync(0xffffffffu, t2, o);
        t3 += __shfl_xor_sync(0xffffffffu, t3, o);
    }

    if (valid && sl < 4) {
        const float th = (sl == 0) ? t0 : (sl == 1) ? t1 : (sl == 2) ? t2 : t3;
        g_scores[(size_t)e * 4 + sl] = th + g_kb[(size_t)d * 4 + sl];
    }
}

// ============================================================================
// K4b: aggregate kernel — one warp per node; {score load, v gather, exp, fma}.
// ============================================================================
__global__ __launch_bounds__(256) void aggregate_kernel(
    const int* __restrict__ dst,
    const float* __restrict__ Wo, const float* __restrict__ bo,
    float* __restrict__ out, int N)
{
    __shared__ float sWo[128 * 32];
    __shared__ float sbo[32];
    const int tid = threadIdx.x;
    for (int i = tid; i < 1024; i += 256)
        ((float4*)sWo)[i] = ((const float4*)Wo)[i];
    if (tid < 32) sbo[tid] = bo[tid];
    __syncthreads();

    const int lane = tid & 31, warp = tid >> 5;
    const int n = blockIdx.x * 8 + warp;
    if (n >= N) return;

    const int hl = lane >> 3;
    const int e0 = g_rowptr[n], e1 = g_rowptr[n + 1];

    float  m    = -1e30f;
    float  sexp = 0.f;
    float4 acc  = make_float4(0.f, 0.f, 0.f, 0.f);

    int e = e0;
#pragma unroll 1
    for (; e + 4 <= e1; e += 4) {
        const int d0 = dst[e],     d1 = dst[e + 1];
        const int d2 = dst[e + 2], d3 = dst[e + 3];
        const float s0 = g_scores[(size_t)(e    ) * 4 + hl];
        const float s1 = g_scores[(size_t)(e + 1) * 4 + hl];
        const float s2 = g_scores[(size_t)(e + 2) * 4 + hl];
        const float s3 = g_scores[(size_t)(e + 3) * 4 + hl];
        const uint2 r0 = *(const uint2*)(g_vh + (size_t)d0 * 128 + lane * 4);
        const uint2 r1 = *(const uint2*)(g_vh + (size_t)d1 * 128 + lane * 4);
        const uint2 r2 = *(const uint2*)(g_vh + (size_t)d2 * 128 + lane * 4);
        const uint2 r3 = *(const uint2*)(g_vh + (size_t)d3 * 128 + lane * 4);

        const float mnew = fmaxf(fmaxf(m, fmaxf(s0, s1)), fmaxf(s2, s3));
        const float scale = __expf(m - mnew);
        const float w0 = __expf(s0 - mnew);
        const float w1 = __expf(s1 - mnew);
        const float w2 = __expf(s2 - mnew);
        const float w3 = __expf(s3 - mnew);
        sexp = fmaf(sexp, scale, (w0 + w1) + (w2 + w3));

        float2 p0 = __half22float2(*(const __half2*)&r0.x);
        float2 p1 = __half22float2(*(const __half2*)&r1.x);
        float2 p2 = __half22float2(*(const __half2*)&r2.x);
        float2 p3 = __half22float2(*(const __half2*)&r3.x);
        acc.x = fmaf(acc.x, scale, fmaf(w0, p0.x, w1 * p1.x) + fmaf(w2, p2.x, w3 * p3.x));
        acc.y = fmaf(acc.y, scale, fmaf(w0, p0.y, w1 * p1.y) + fmaf(w2, p2.y, w3 * p3.y));
        p0 = __half22float2(*(const __half2*)&r0.y);
        p1 = __half22float2(*(const __half2*)&r1.y);
        p2 = __half22float2(*(const __half2*)&r2.y);
        p3 = __half22float2(*(const __half2*)&r3.y);
        acc.z = fmaf(acc.z, scale, fmaf(w0, p0.x, w1 * p1.x) + fmaf(w2, p2.x, w3 * p3.x));
        acc.w = fmaf(acc.w, scale, fmaf(w0, p0.y, w1 * p1.y) + fmaf(w2, p2.y, w3 * p3.y));
        m = mnew;
    }
#pragma unroll 1
    for (; e < e1; e++) {
        const int d0 = dst[e];
        const float s0 = g_scores[(size_t)e * 4 + hl];
        const uint2 r0 = *(const uint2*)(g_vh + (size_t)d0 * 128 + lane * 4);
        const float mnew  = fmaxf(m, s0);
        const float scale = __expf(m - mnew);
        const float w0    = __expf(s0 - mnew);
        sexp = fmaf(sexp, scale, w0);
        const float2 p0 = __half22float2(*(const __half2*)&r0.x);
        const float2 p1 = __half22float2(*(const __half2*)&r0.y);
        acc.x = fmaf(acc.x, scale, w0 * p0.x);
        acc.y = fmaf(acc.y, scale, w0 * p0.y);
        acc.z = fmaf(acc.z, scale, w0 * p1.x);
        acc.w = fmaf(acc.w, scale, w0 * p1.y);
        m = mnew;
    }

    const float inv = (sexp > 0.f) ? (1.0f / sexp) : 0.f;
    acc.x *= inv; acc.y *= inv; acc.z *= inv; acc.w *= inv;

    float o = sbo[lane];
#pragma unroll
    for (int p = 0; p < 32; p++) {
        const float ax = __shfl_sync(0xffffffffu, acc.x, p);
        const float ay = __shfl_sync(0xffffffffu, acc.y, p);
        const float az = __shfl_sync(0xffffffffu, acc.z, p);
        const float aw = __shfl_sync(0xffffffffu, acc.w, p);
        o = fmaf(ax, sWo[(4 * p + 0) * 32 + lane], o);
        o = fmaf(ay, sWo[(4 * p + 1) * 32 + lane], o);
        o = fmaf(az, sWo[(4 * p + 2) * 32 + lane], o);
        o = fmaf(aw, sWo[(4 * p + 3) * 32 + lane], o);
    }
    out[n * 32 + lane] = fmaxf(o, 0.f);
}

// ============================================================================
// launch
// ============================================================================
extern "C" void kernel_launch(void* const* d_in, const int* in_sizes, int n_in,
                              void* d_out, int out_size)
{
    const float* X  = (const float*)d_in[0];
    const int*   EI = (const int*)  d_in[1];   // [2,E]: src then dst
    const float* EF = (const float*)d_in[2];
    const float* Wq = (const float*)d_in[3];
    const float* bq = (const float*)d_in[4];
    const float* Wk = (const float*)d_in[5];
    const float* bk = (const float*)d_in[6];
    const float* Wv = (const float*)d_in[7];
    const float* bv = (const float*)d_in[8];
    const float* We = (const float*)d_in[9];
    const float* be = (const float*)d_in[10];
    const float* Wo = (const float*)d_in[11];
    const float* bo = (const float*)d_in[12];

    const int N = in_sizes[0] / 128;
    const int E = in_sizes[1] / 2;

    dim3 g1((N + 127) / 128, 3);
    qkv_gemm_kernel<<<g1, 256>>>(X, Wq, bq, Wk, bk, Wv, bv, N);
    mk_kernel<<<(N + 15) / 16, 256>>>(We, be, N);
    rowptr_kernel<<<(N + 1 + 255) / 256, 256>>>(EI, E, N);
    score_kernel<<<(E + 31) / 32, 256>>>(EF, EI, EI + E, E);
    aggregate_kernel<<<(N + 7) / 8, 256>>>(EI + E, Wo, bo, (float*)d_out, N);
}